// round 4
// baseline (speedup 1.0000x reference)
#include <cuda_runtime.h>

// Fused local NCC loss (kernel=3, zero 'same' padding) over 192^3 f32 volumes.
// Lanes along d (coalesced), H_OUT=2 h-outputs per thread, w marched with a
// 2-slot running-sum state (T = prev two planes summed, B = prev plane),
// d-window via warp shuffles at emit time. (I,J),(II,JJ),(IJ0,IJ1-style)
// component math in packed f32x2 where possible.

#define SZ   192
#define SZ2  (SZ * SZ)
#define NTOT (SZ * SZ * SZ)

#define D_OUT  30             // d outputs per warp (lanes 1..30)
#define GX     7              // ceil(192/30)
#define H_OUT  2              // h outputs per thread
#define BY     4              // h-groups per block -> h tile 8
#define GY     24             // 192/8
#define WCHUNK 16             // w outputs per block
#define GZ     12             // 192/16
#define NBLK   (GX * GY * GZ) // 2016

typedef unsigned long long u64;

__device__ float        g_partial[NBLK];
__device__ unsigned int g_count = 0;

__device__ __forceinline__ u64 pk2(float lo, float hi) {
    u64 r; asm("mov.b64 %0, {%1, %2};" : "=l"(r) : "f"(lo), "f"(hi)); return r;
}
__device__ __forceinline__ void upk2(u64 v, float& lo, float& hi) {
    asm("mov.b64 {%0, %1}, %2;" : "=f"(lo), "=f"(hi) : "l"(v));
}
__device__ __forceinline__ u64 add2(u64 a, u64 b) {
    u64 r; asm("add.rn.f32x2 %0, %1, %2;" : "=l"(r) : "l"(a), "l"(b)); return r;
}
__device__ __forceinline__ u64 mul2(u64 a, u64 b) {
    u64 r; asm("mul.rn.f32x2 %0, %1, %2;" : "=l"(r) : "l"(a), "l"(b)); return r;
}

struct Plane {               // 10 regs: h-window sums, d/w not yet applied
    u64   P[H_OUT];          // packed (sumI, sumJ)
    u64   Q[H_OUT];          // packed (sumII, sumJJ)
    float R[H_OUT];          // sumIJ
};

__device__ __forceinline__ void compute_plane(
    const float* __restrict__ pred, const float* __restrict__ targ,
    int base0, int wp, unsigned m, Plane& C)
{
    if ((unsigned)wp >= (unsigned)SZ) {
        #pragma unroll
        for (int j = 0; j < H_OUT; j++) { C.P[j] = 0ull; C.Q[j] = 0ull; C.R[j] = 0.f; }
        return;
    }
    const int pofs = base0 + wp * SZ;
    u64 p[4], q[4]; float r[4];
    #pragma unroll
    for (int i = 0; i < 4; i++) {
        float I = 0.f, J = 0.f;
        if ((m >> i) & 1u) {
            const int o = pofs + i * SZ2;
            I = pred[o];
            J = targ[o];
        }
        p[i] = pk2(I, J);
        q[i] = mul2(p[i], p[i]);
        r[i] = I * J;
    }
    // out0 (h0):  rows 0,1,2 ; out1 (h0+1): rows 1,2,3
    u64 mP = add2(p[1], p[2]);
    C.P[0] = add2(mP, p[0]);
    C.P[1] = add2(mP, p[3]);
    u64 mQ = add2(q[1], q[2]);
    C.Q[0] = add2(mQ, q[0]);
    C.Q[1] = add2(mQ, q[3]);
    float mR = r[1] + r[2];
    C.R[0] = mR + r[0];
    C.R[1] = mR + r[3];
}

__device__ __forceinline__ void plane_sum(Plane& T, const Plane& B, const Plane& C)
{
    #pragma unroll
    for (int j = 0; j < H_OUT; j++) {
        T.P[j] = add2(B.P[j], C.P[j]);
        T.Q[j] = add2(B.Q[j], C.Q[j]);
        T.R[j] = B.R[j] + C.R[j];
    }
}

// Runs on ALL lanes (contains warp shuffles). Caller predicates accumulation.
__device__ __forceinline__ float emit2(const Plane& T, const Plane& C)
{
    float v = 0.f;
    const float inv_kv = 1.0f / 27.0f;
    #pragma unroll
    for (int j = 0; j < H_OUT; j++) {
        u64   Pw = add2(T.P[j], C.P[j]);
        u64   Qw = add2(T.Q[j], C.Q[j]);
        float Rw = T.R[j] + C.R[j];
        // d-window: lanes hold consecutive d columns
        u64 Pu = __shfl_up_sync(0xffffffffu, Pw, 1);
        u64 Pd = __shfl_down_sync(0xffffffffu, Pw, 1);
        Pw = add2(add2(Pu, Pw), Pd);
        u64 Qu = __shfl_up_sync(0xffffffffu, Qw, 1);
        u64 Qd = __shfl_down_sync(0xffffffffu, Qw, 1);
        Qw = add2(add2(Qu, Qw), Qd);
        float Ru = __shfl_up_sync(0xffffffffu, Rw, 1);
        float Rd = __shfl_down_sync(0xffffffffu, Rw, 1);
        Rw = Ru + Rw + Rd;

        float sI, sJ, sII, sJJ;
        upk2(Pw, sI, sJ);
        upk2(Qw, sII, sJJ);
        float m1 = sI * inv_kv;
        float m2 = sJ * inv_kv;
        float cross = fmaf(-m2, sI, Rw);    // sum((I-uI)(J-uJ))
        float Iv    = fmaf(-m1, sI, sII);   // sum((I-uI)^2)
        float Jv    = fmaf(-m2, sJ, sJJ);   // sum((J-uJ)^2)
        float den   = fmaf(Iv, Jv, 1e-5f);
        v += __fdividef(cross * cross, den);
    }
    return v;
}

__global__ __launch_bounds__(128, 8)
void lncc_fused_kernel(const float* __restrict__ pred,
                       const float* __restrict__ targ,
                       float* __restrict__ out)
{
    const int lane = threadIdx.x;                       // 0..31 along d
    const int dcol = blockIdx.x * D_OUT + lane - 1;     // loaded d column
    const int h0   = blockIdx.y * (BY * H_OUT) + threadIdx.y * H_OUT;
    const int w0   = blockIdx.z * WCHUNK;

    const bool dok = (dcol >= 0) && (dcol < SZ);
    unsigned m = 0;
    #pragma unroll
    for (int i = 0; i < 4; i++) {
        int hh = h0 - 1 + i;
        if (dok && hh >= 0 && hh < SZ) m |= (1u << i);
    }
    const int  base0   = (h0 - 1) * SZ2 + dcol;
    const bool emit_ok = (lane >= 1) && (lane <= D_OUT) && (dcol < SZ);

    Plane T, B, C;
    float acc = 0.f;

    // Prologue: planes w0-1 and w0.
    compute_plane(pred, targ, base0, w0 - 1, m, B);
    T = B;                                   // first emit only needs w0-1 onward
    compute_plane(pred, targ, base0, w0, m, C);
    plane_sum(T, B, C);                      // T = plane(w0-1)+plane(w0)
    B = C;

    // Main: wp = w0+1 .. w0+WCHUNK ; emit output wp-1 = T + plane(wp).
    #pragma unroll
    for (int t = 1; t <= WCHUNK; t++) {
        compute_plane(pred, targ, base0, w0 + t, m, C);
        float v = emit2(T, C);
        if (emit_ok) acc += v;
        plane_sum(T, B, C);
        B = C;
    }

    // ---- deterministic in-kernel reduction ----
    __shared__ float  sred[128];
    __shared__ double dred[128];
    __shared__ unsigned int s_last;
    const int tid = threadIdx.y * 32 + lane;

    sred[tid] = acc;
    __syncthreads();
    #pragma unroll
    for (int s = 64; s > 0; s >>= 1) {
        if (tid < s) sred[tid] += sred[tid + s];
        __syncthreads();
    }
    if (tid == 0) {
        const int blin = blockIdx.x + GX * (blockIdx.y + GY * blockIdx.z);
        g_partial[blin] = sred[0];
        __threadfence();
        unsigned old = atomicAdd(&g_count, 1u);
        s_last = (old == (unsigned)(NBLK - 1)) ? 1u : 0u;
    }
    __syncthreads();

    if (s_last) {
        double s = 0.0;
        for (int i = tid; i < NBLK; i += 128)
            s += (double)g_partial[i];
        dred[tid] = s;
        __syncthreads();
        #pragma unroll
        for (int k = 64; k > 0; k >>= 1) {
            if (tid < k) dred[tid] += dred[tid + k];
            __syncthreads();
        }
        if (tid == 0) {
            out[0] = (float)(-dred[0] / (double)NTOT);
            g_count = 0;   // reset for the next (graph-replayed) call
        }
    }
}

extern "C" void kernel_launch(void* const* d_in, const int* in_sizes, int n_in,
                              void* d_out, int out_size) {
    const float* pred = (const float*)d_in[0];
    const float* targ = (const float*)d_in[1];
    dim3 grid(GX, GY, GZ);
    dim3 block(32, BY, 1);
    lncc_fused_kernel<<<grid, block>>>(pred, targ, (float*)d_out);
}

// round 5
// speedup vs baseline: 1.1403x; 1.1403x over previous
#include <cuda_runtime.h>

// Fused local NCC loss (kernel=3, zero 'same' padding) over 192^3 f32 volumes.
// One warp spans the full d=192: each lane owns 3 float2 packs at
// d = {2*lane, 64+2*lane, 128+2*lane} (coalesced LDG.64). H=1 row per warp,
// rows h-1,h,h+1 via per-row pointers (zero-buffer redirect at h edges).
// w marched with a 2-plane T-scheme ring (T = sum of prev two planes),
// planes built in place (no copies). d-window seams via publish-SEL +
// index-shuffle (2 SEL + 2 SHFL per component per pack).

#define SZ    192
#define SZ2   (SZ * SZ)
#define NTOT  (SZ * SZ * SZ)
#define WCHUNK 12
#define GY     96              // 192 h rows / 2 warps per block
#define GZ     16              // 192 / WCHUNK
#define NBLK   (GY * GZ)       // 1536

typedef unsigned long long u64;

__device__ float        g_zero[4608];          // static zero (BSS) pad source
__device__ float        g_partial[NBLK];
__device__ unsigned int g_count = 0;

__device__ __forceinline__ u64 add2(u64 a, u64 b) {
    u64 r; asm("add.rn.f32x2 %0, %1, %2;" : "=l"(r) : "l"(a), "l"(b)); return r;
}
__device__ __forceinline__ u64 mul2(u64 a, u64 b) {
    u64 r; asm("mul.rn.f32x2 %0, %1, %2;" : "=l"(r) : "l"(a), "l"(b)); return r;
}
__device__ __forceinline__ u64 fma2(u64 a, u64 b, u64 c) {
    u64 r; asm("fma.rn.f32x2 %0, %1, %2, %3;" : "=l"(r) : "l"(a), "l"(b), "l"(c)); return r;
}
__device__ __forceinline__ void upk2(u64 v, float& lo, float& hi) {
    asm("mov.b64 {%0, %1}, %2;" : "=f"(lo), "=f"(hi) : "l"(v));
}

struct PS { u64 v[5][3]; };   // components {I,J,II,JJ,IJ} x packs {s=0,1,2}

// Build plane sums over the 3 h-rows. foff = float offset of this plane
// relative to the (already w-positioned) row pointers.
__device__ __forceinline__ void build_plane(
    PS& C, const float* const (&pI)[3], const float* const (&pJ)[3],
    int foff, int wp)
{
    if ((unsigned)wp >= (unsigned)SZ) {
        #pragma unroll
        for (int c = 0; c < 5; c++)
            #pragma unroll
            for (int s = 0; s < 3; s++) C.v[c][s] = 0ull;
        return;
    }
    #pragma unroll
    for (int s = 0; s < 3; s++) {
        u64 aI, aJ, aII, aJJ, aIJ;
        #pragma unroll
        for (int r = 0; r < 3; r++) {
            u64 I = *(const u64*)(pI[r] + foff + 64 * s);
            u64 J = *(const u64*)(pJ[r] + foff + 64 * s);
            if (r == 0) {
                aI = I; aJ = J;
                aII = mul2(I, I); aJJ = mul2(J, J); aIJ = mul2(I, J);
            } else {
                aI = add2(aI, I); aJ = add2(aJ, J);
                aII = fma2(I, I, aII); aJJ = fma2(J, J, aJJ); aIJ = fma2(I, J, aIJ);
            }
        }
        C.v[0][s] = aI; C.v[1][s] = aJ; C.v[2][s] = aII; C.v[3][s] = aJJ; C.v[4][s] = aIJ;
    }
}

// Emit one output w-plane: window sums = T + Cr; also updates T = Bo + Cr.
__device__ __forceinline__ float emit(PS& T, const PS& Bo, const PS& Cr, int lane)
{
    float o[5][6];
    #pragma unroll
    for (int c = 0; c < 5; c++) {
        float lo[3], hi[3];
        #pragma unroll
        for (int s = 0; s < 3; s++) {
            u64 Pw = add2(T.v[c][s], Cr.v[c][s]);
            T.v[c][s] = add2(Bo.v[c][s], Cr.v[c][s]);
            upk2(Pw, lo[s], hi[s]);
        }
        #pragma unroll
        for (int s = 0; s < 3; s++) {
            // prev = s(d0-1): lane l-1's hi[s]; lane0 <- lane31's hi[s-1] (0 if s==0)
            float pubp = (lane == 31) ? (s ? hi[s - 1] : 0.f) : hi[s];
            float prev = __shfl_sync(0xffffffffu, pubp, (lane + 31) & 31);
            // next = s(d1+1): lane l+1's lo[s]; lane31 <- lane0's lo[s+1] (0 if s==2)
            float pubn = (lane == 0) ? (s < 2 ? lo[s + 1] : 0.f) : lo[s];
            float next = __shfl_sync(0xffffffffu, pubn, (lane + 1) & 31);
            float t = lo[s] + hi[s];
            o[c][2 * s]     = t + prev;
            o[c][2 * s + 1] = t + next;
        }
    }
    float acc = 0.f;
    const float ninv = -1.0f / 27.0f;
    #pragma unroll
    for (int i = 0; i < 6; i++) {
        float sI = o[0][i], sJ = o[1][i], sII = o[2][i], sJJ = o[3][i], sIJ = o[4][i];
        float m1n = sI * ninv;
        float m2n = sJ * ninv;
        float cross = fmaf(m2n, sI, sIJ);     // sum((I-uI)(J-uJ))
        float Iv    = fmaf(m1n, sI, sII);     // sum((I-uI)^2)
        float Jv    = fmaf(m2n, sJ, sJJ);     // sum((J-uJ)^2)
        float den   = fmaf(Iv, Jv, 1e-5f);
        acc += __fdividef(cross * cross, den);
    }
    return acc;
}

__global__ __launch_bounds__(64, 6)
void lncc_fused_kernel(const float* __restrict__ pred,
                       const float* __restrict__ targ,
                       float* __restrict__ out)
{
    const int lane = threadIdx.x;                 // 0..31
    const int h    = blockIdx.y * 2 + threadIdx.y; // one h row per warp
    const int w0   = blockIdx.z * WCHUNK;

    // Per-row pointers (w-positioned at plane w0-1, lane-offset applied);
    // out-of-range h rows redirect into the static zero buffer.
    const float* pI[3];
    const float* pJ[3];
    #pragma unroll
    for (int r = 0; r < 3; r++) {
        int hh = h - 1 + r;
        bool ok = (hh >= 0) && (hh < SZ);
        long off = (long)hh * SZ2 + (long)(w0 - 1) * SZ + 2 * lane;
        pI[r] = ok ? pred + off : g_zero + 2 * lane;
        pJ[r] = ok ? targ + off : g_zero + 2 * lane;
    }

    PS T, B0, B1;
    int wp = w0 - 1;
    build_plane(B0, pI, pJ, 0,  wp);        // plane k=0
    build_plane(B1, pI, pJ, SZ, wp + 1);    // plane k=1
    #pragma unroll
    for (int c = 0; c < 5; c++)
        #pragma unroll
        for (int s = 0; s < 3; s++)
            T.v[c][s] = add2(B0.v[c][s], B1.v[c][s]);
    #pragma unroll
    for (int r = 0; r < 3; r++) { pI[r] += 2 * SZ; pJ[r] += 2 * SZ; }
    wp += 2;

    float acc = 0.f;
    // planes k=2..13 (12 emits), pairs: C alternates into B0/B1 (in-place ring)
    for (int t = 0; t < 6; t++) {
        build_plane(B0, pI, pJ, 0, wp);        // plane k even: Cr=B0, Bo=B1
        acc += emit(T, B1, B0, lane);
        build_plane(B1, pI, pJ, SZ, wp + 1);   // plane k odd:  Cr=B1, Bo=B0
        acc += emit(T, B0, B1, lane);
        #pragma unroll
        for (int r = 0; r < 3; r++) { pI[r] += 2 * SZ; pJ[r] += 2 * SZ; }
        wp += 2;
    }

    // ---- deterministic in-kernel reduction ----
    __shared__ float  sred[64];
    __shared__ double dred[64];
    __shared__ unsigned int s_last;
    const int tid = threadIdx.y * 32 + lane;

    sred[tid] = acc;
    __syncthreads();
    #pragma unroll
    for (int s = 32; s > 0; s >>= 1) {
        if (tid < s) sred[tid] += sred[tid + s];
        __syncthreads();
    }
    if (tid == 0) {
        const int blin = blockIdx.y + GY * blockIdx.z;
        g_partial[blin] = sred[0];
        __threadfence();
        unsigned old = atomicAdd(&g_count, 1u);
        s_last = (old == (unsigned)(NBLK - 1)) ? 1u : 0u;
    }
    __syncthreads();

    if (s_last) {
        double s = 0.0;
        for (int i = tid; i < NBLK; i += 64)
            s += (double)g_partial[i];
        dred[tid] = s;
        __syncthreads();
        #pragma unroll
        for (int k = 32; k > 0; k >>= 1) {
            if (tid < k) dred[tid] += dred[tid + k];
            __syncthreads();
        }
        if (tid == 0) {
            out[0] = (float)(-dred[0] / (double)NTOT);
            g_count = 0;   // reset for the next (graph-replayed) call
        }
    }
}

extern "C" void kernel_launch(void* const* d_in, const int* in_sizes, int n_in,
                              void* d_out, int out_size) {
    const float* pred = (const float*)d_in[0];
    const float* targ = (const float*)d_in[1];
    dim3 grid(1, GY, GZ);
    dim3 block(32, 2, 1);
    lncc_fused_kernel<<<grid, block>>>(pred, targ, (float*)d_out);
}